// round 16
// baseline (speedup 1.0000x reference)
#include <cuda_runtime.h>
#include <cuda_fp16.h>

#define RES 512
#define RANK 32
#define CELLS (RES * RES)
#define N_POINTS (8192 * 128)

// e5m2 dup-pair layout: per plane, per cell (y,x): 64 bytes.
// Word k of 16B group j holds bytes [r@x0, r@x1, r+1@x0, r+1@x1], r = 8j+2k.
// e5m2 byte b decodes EXACTLY to the fp16 with bits (b << 8).
// Plane stride = CELLS*64 = 0x1000000 bytes.
__device__ unsigned char g_tp[3][(size_t)CELLS * 2 * RANK];

// Per-point packed head state: 8 u32 per point (32 B):
// [o_xy|f, o_xz|f, o_yz|f, w_xy, w_xz, w_yz, pad, pad]
// offset words: byte offset incl. plane stride; bit 0 = (y0<511) flag.
// w words: packed half2 (wx, wy).
__device__ unsigned int g_head[(size_t)N_POINTS * 8];

// Encoded per-dim bbox of raw pts. Static init; graph replays are idempotent.
__device__ unsigned int g_bbox[6] = {0xFFFFFFFFu, 0xFFFFFFFFu, 0xFFFFFFFFu, 0u, 0u, 0u};

// Affine map: grid = p * g_map[0].{x,y,z} + g_map[1].{x,y,z}
__device__ float4 g_map[2];

__device__ __forceinline__ unsigned int encodeF(float f) {
    unsigned int b = __float_as_uint(f);
    return (b & 0x80000000u) ? ~b : (b | 0x80000000u);
}
__device__ __forceinline__ float decodeF(unsigned int u) {
    return (u & 0x80000000u) ? __uint_as_float(u ^ 0x80000000u)
                             : __uint_as_float(~u);
}

// HW pack-convert: 2 x f32 -> packed e5m2 pair.
__device__ __forceinline__ unsigned short enc2_e5m2(float hi, float lo) {
    unsigned short r;
    asm("cvt.rn.satfinite.e5m2x2.f32 %0, %1, %2;" : "=h"(r) : "f"(hi), "f"(lo));
    return r;
}

// ---------------------------------------------------------------------------
// Kernel 1: bbox + g_map (thread 0). One group (3 float4 = 4 pts) per thread.
// ---------------------------------------------------------------------------
__global__ void __launch_bounds__(256) bbox_kernel(const float4* __restrict__ pts4,
                                                   const float* __restrict__ aabb) {
    const int g = blockIdx.x * 256 + threadIdx.x;
    if (g == 0) {
        float k[3], o[3];
#pragma unroll
        for (int d = 0; d < 3; d++) {
            const float a0 = aabb[d], a1 = aabb[3 + d];
            k[d] = (float)(RES - 1) / (a1 - a0);
            o[d] = -a0 * k[d];
        }
        g_map[0] = make_float4(k[0], k[1], k[2], 0.0f);
        g_map[1] = make_float4(o[0], o[1], o[2], 0.0f);
    }

    const float4 a = __ldg(&pts4[3 * g + 0]);
    const float4 b = __ldg(&pts4[3 * g + 1]);
    const float4 c = __ldg(&pts4[3 * g + 2]);
    const unsigned int FULL = 0xffffffffu;
    const unsigned int rmnx = __reduce_min_sync(FULL, encodeF(fminf(fminf(a.x, a.w), fminf(b.z, c.y))));
    const unsigned int rmxx = __reduce_max_sync(FULL, encodeF(fmaxf(fmaxf(a.x, a.w), fmaxf(b.z, c.y))));
    const unsigned int rmny = __reduce_min_sync(FULL, encodeF(fminf(fminf(a.y, b.x), fminf(b.w, c.z))));
    const unsigned int rmxy = __reduce_max_sync(FULL, encodeF(fmaxf(fmaxf(a.y, b.x), fmaxf(b.w, c.z))));
    const unsigned int rmnz = __reduce_min_sync(FULL, encodeF(fminf(fminf(a.z, b.y), fminf(c.x, c.w))));
    const unsigned int rmxz = __reduce_max_sync(FULL, encodeF(fmaxf(fmaxf(a.z, b.y), fmaxf(c.x, c.w))));

    __shared__ unsigned int smn[3], smx[3];
    if (threadIdx.x < 3) { smn[threadIdx.x] = 0xFFFFFFFFu; smx[threadIdx.x] = 0u; }
    __syncthreads();
    if ((threadIdx.x & 31) == 0) {
        atomicMin(&smn[0], rmnx);
        atomicMin(&smn[1], rmny);
        atomicMin(&smn[2], rmnz);
        atomicMax(&smx[0], rmxx);
        atomicMax(&smx[1], rmxy);
        atomicMax(&smx[2], rmxz);
    }
    __syncthreads();
    if (threadIdx.x < 3) {
        atomicMin(&g_bbox[threadIdx.x], smn[threadIdx.x]);
        atomicMax(&g_bbox[3 + threadIdx.x], smx[threadIdx.x]);
    }
}

// ---------------------------------------------------------------------------
// Kernel 2: per-point head precompute (1 thread/point).
// ---------------------------------------------------------------------------
__device__ __forceinline__ uint2 head_plane(float gx, float gy, unsigned int plane_off) {
    const float wx = gx - floorf(gx);
    const float wy = gy - floorf(gy);
    const int x0 = min(max(__float2int_rd(gx), 0), RES - 1);
    const int y0 = min(max(__float2int_rd(gy), 0), RES - 1);
    const unsigned int f = (y0 < RES - 1) ? 1u : 0u;
    const unsigned int o = ((unsigned int)((y0 << 9) + x0) << 6) + plane_off + f;
    const __half2 w = __floats2half2_rn(wx, wy);
    uint2 r;
    r.x = o;
    r.y = *reinterpret_cast<const unsigned int*>(&w);
    return r;
}

__global__ void __launch_bounds__(256) head_kernel(const float* __restrict__ pts) {
    const int i = blockIdx.x * 256 + threadIdx.x;
    const float px = __ldg(&pts[3 * i + 0]);
    const float py = __ldg(&pts[3 * i + 1]);
    const float pz = __ldg(&pts[3 * i + 2]);

    const float4 K = g_map[0];
    const float4 O = g_map[1];
    const float gx = fmaf(px, K.x, O.x);
    const float gy = fmaf(py, K.y, O.y);
    const float gz = fmaf(pz, K.z, O.z);

    const uint2 a = head_plane(gx, gy, 0u);
    const uint2 b = head_plane(gx, gz, 0x1000000u);
    const uint2 c = head_plane(gy, gz, 0x2000000u);

    unsigned int* dst = &g_head[(size_t)i * 8];
    uint4 h1;
    h1.x = a.x; h1.y = b.x; h1.z = c.x; h1.w = a.y;
    *reinterpret_cast<uint4*>(dst) = h1;
    uint2 h2;
    h2.x = b.y; h2.y = c.y;
    *reinterpret_cast<uint2*>(dst + 4) = h2;
}

// ---------------------------------------------------------------------------
// Kernel 3: [RANK,H,W] f32 -> e5m2 dup-pair layout, bbox-gated.
// ---------------------------------------------------------------------------
__global__ void __launch_bounds__(256) transpose_kernel(const float* __restrict__ gxy,
                                                        const float* __restrict__ gxz,
                                                        const float* __restrict__ gyz,
                                                        const float* __restrict__ aabb) {
    const int plane = blockIdx.y;
    const int c0 = blockIdx.x * 64;
    const int row = c0 >> 9;
    const int col0 = c0 & (RES - 1);

    const int cdim = (plane == 2) ? 1 : 0;
    const int rdim = (plane == 0) ? 1 : 2;

    {   // bbox gate
        const float a0c = aabb[cdim], sc = (float)(RES - 1) / (aabb[3 + cdim] - aabb[cdim]);
        const float a0r = aabb[rdim], sr = (float)(RES - 1) / (aabb[3 + rdim] - aabb[rdim]);
        const float gminc = (decodeF(g_bbox[cdim]) - a0c) * sc;
        const float gmaxc = (decodeF(g_bbox[3 + cdim]) - a0c) * sc;
        const float gminr = (decodeF(g_bbox[rdim]) - a0r) * sr;
        const float gmaxr = (decodeF(g_bbox[3 + rdim]) - a0r) * sr;
        const int cmin = min(max(__float2int_rd(gminc), 0), RES - 1);
        const int cmax = min(min(max(__float2int_rd(gmaxc), 0), RES - 1) + 1, RES - 1);
        const int rmin = min(max(__float2int_rd(gminr), 0), RES - 1);
        const int rmax = min(min(max(__float2int_rd(gmaxr), 0), RES - 1) + 1, RES - 1);
        if (row < rmin || row > rmax || col0 > cmax || col0 + 63 < cmin) return;
    }

    __shared__ float tile[RANK][67];
    const float* __restrict__ src = (plane == 0) ? gxy : (plane == 1) ? gxz : gyz;

    const int t = threadIdx.x;

#pragma unroll
    for (int i = 0; i < 2; i++) {
        const int q = t + i * 256;
        const int r = q >> 4;
        const int c4 = (q & 15) << 2;
        const float4 v = *reinterpret_cast<const float4*>(&src[(size_t)r * CELLS + c0 + c4]);
        tile[r][c4 + 0] = v.x;
        tile[r][c4 + 1] = v.y;
        tile[r][c4 + 2] = v.z;
        tile[r][c4 + 3] = v.w;
    }
    if (t < RANK) {
        const int srccol = (col0 + 64 <= RES - 1) ? (c0 + 64) : (c0 + 63);
        tile[t][64] = src[(size_t)t * CELLS + srccol];
    }
    __syncthreads();

    {
        const int cell = t >> 2;
        const int j = t & 3;
        const int xg = col0 + cell;
        const int nb = (xg < RES - 1) ? cell + 1 : cell;
        uint4 w;
        unsigned int* wp = &w.x;
#pragma unroll
        for (int k = 0; k < 4; k++) {
            const int r0 = 8 * j + 2 * k;
            const unsigned short lo16 = enc2_e5m2(tile[r0][nb], tile[r0][cell]);
            const unsigned short hi16 = enc2_e5m2(tile[r0 + 1][nb], tile[r0 + 1][cell]);
            wp[k] = ((unsigned int)hi16 << 16) | (unsigned int)lo16;
        }
        *reinterpret_cast<uint4*>(&g_tp[plane][((size_t)(c0 + cell) << 6) + (j << 4)]) = w;
    }
}

// ---------------------------------------------------------------------------
// Kernel 4: triplane sample. 4 lanes/point; lane j = ranks 8j..8j+7.
// Head state is precomputed: 2 broadcast loads + trivial decode.
// ---------------------------------------------------------------------------
__device__ __forceinline__ __half2 as_h2(unsigned int u) {
    return *reinterpret_cast<__half2*>(&u);
}

__device__ __forceinline__ void plane_sample(const uint4& E, const uint4& F,
                                             __half2 w00, __half2 w01,
                                             __half2 w10, __half2 w11,
                                             __half2 s2[4]) {
    const unsigned int* e = &E.x;
    const unsigned int* f = &F.x;
#pragma unroll
    for (int k = 0; k < 4; k++) {
        const unsigned int ex0 = __byte_perm(e[k], 0, 0x2404);  // (r@x0, r+1@x0)
        const unsigned int ex1 = e[k] & 0xFF00FF00u;            // (r@x1, r+1@x1)
        const unsigned int fx0 = __byte_perm(f[k], 0, 0x2404);
        const unsigned int fx1 = f[k] & 0xFF00FF00u;
        __half2 s = __hmul2(as_h2(ex0), w00);
        s = __hfma2(as_h2(ex1), w01, s);
        s = __hfma2(as_h2(fx0), w10, s);
        s2[k] = __hfma2(as_h2(fx1), w11, s);
    }
}

__global__ void __launch_bounds__(256, 8) sample_kernel(float* __restrict__ out) {
    const int tid = blockIdx.x * blockDim.x + threadIdx.x;
    const int j = tid & 3;             // rank octet 0..3 (8 ranks each)
    const int point = tid >> 2;        // 4 lanes per point
    const unsigned int lo = (unsigned int)j << 4;

    const unsigned int* hp = &g_head[(size_t)point * 8];
    const uint4 H1 = *reinterpret_cast<const uint4*>(hp);
    const uint2 H2 = *reinterpret_cast<const uint2*>(hp + 4);

    // Decode offsets: u = o|f; o0 = u+lo-f; o1 = o0 + f*32768.
    const unsigned int fa = H1.x & 1u;
    const unsigned int oa0 = H1.x + lo - fa;
    const unsigned int oa1 = oa0 + (fa << 15);
    const unsigned int fb = H1.y & 1u;
    const unsigned int ob0 = H1.y + lo - fb;
    const unsigned int ob1 = ob0 + (fb << 15);
    const unsigned int fc = H1.z & 1u;
    const unsigned int oc0 = H1.z + lo - fc;
    const unsigned int oc1 = oc0 + (fc << 15);

    const char* __restrict__ B = reinterpret_cast<const char*>(g_tp);
    const uint4 E0 = *reinterpret_cast<const uint4*>(B + oa0);
    const uint4 F0 = *reinterpret_cast<const uint4*>(B + oa1);
    const uint4 E1 = *reinterpret_cast<const uint4*>(B + ob0);
    const uint4 F1 = *reinterpret_cast<const uint4*>(B + ob1);
    const uint4 E2 = *reinterpret_cast<const uint4*>(B + oc0);
    const uint4 F2 = *reinterpret_cast<const uint4*>(B + oc1);

    // Broadcast weights from packed (wx,wy) words
    const __half2 wx2_0 = as_h2(__byte_perm(H1.w, H1.w, 0x1010));
    const __half2 wy2_0 = as_h2(__byte_perm(H1.w, H1.w, 0x3232));
    const __half2 wx2_1 = as_h2(__byte_perm(H2.x, H2.x, 0x1010));
    const __half2 wy2_1 = as_h2(__byte_perm(H2.x, H2.x, 0x3232));
    const __half2 wx2_2 = as_h2(__byte_perm(H2.y, H2.y, 0x1010));
    const __half2 wy2_2 = as_h2(__byte_perm(H2.y, H2.y, 0x3232));

    const __half2 ONE = __float2half2_rn(1.0f);
    const __half2 ox0 = __hsub2(ONE, wx2_0), oy0 = __hsub2(ONE, wy2_0);
    const __half2 ox1 = __hsub2(ONE, wx2_1), oy1 = __hsub2(ONE, wy2_1);
    const __half2 ox2 = __hsub2(ONE, wx2_2), oy2 = __hsub2(ONE, wy2_2);

    __half2 sA[4], sB[4], sC[4];
    plane_sample(E0, F0, __hmul2(ox0, oy0), __hmul2(wx2_0, oy0),
                 __hmul2(ox0, wy2_0), __hmul2(wx2_0, wy2_0), sA);
    plane_sample(E1, F1, __hmul2(ox1, oy1), __hmul2(wx2_1, oy1),
                 __hmul2(ox1, wy2_1), __hmul2(wx2_1, wy2_1), sB);
    plane_sample(E2, F2, __hmul2(ox2, oy2), __hmul2(wx2_2, oy2),
                 __hmul2(ox2, wy2_2), __hmul2(wx2_2, wy2_2), sC);

    __half2 acc = __hmul2(__hmul2(sA[0], sB[0]), sC[0]);
#pragma unroll
    for (int k = 1; k < 4; k++) {
        acc = __hfma2(__hmul2(sA[k], sB[k]), sC[k], acc);
    }
    float sum = __low2float(acc) + __high2float(acc);

    sum += __shfl_xor_sync(0xffffffffu, sum, 1, 4);
    sum += __shfl_xor_sync(0xffffffffu, sum, 2, 4);

    if (j == 0) {
        out[point] = exp2f(sum * 0.045084220f);   // exp(sum/32)
    }
}

extern "C" void kernel_launch(void* const* d_in, const int* in_sizes, int n_in,
                              void* d_out, int out_size) {
    const float* pts  = (const float*)d_in[0];
    const float* gxy  = (const float*)d_in[1];
    const float* gxz  = (const float*)d_in[2];
    const float* gyz  = (const float*)d_in[3];
    const float* aabb = (const float*)d_in[4];
    float* out = (float*)d_out;

    bbox_kernel<<<1024, 256>>>((const float4*)pts, aabb);
    head_kernel<<<N_POINTS / 256, 256>>>(pts);
    transpose_kernel<<<dim3(CELLS / 64, 3), 256>>>(gxy, gxz, gyz, aabb);
    sample_kernel<<<N_POINTS / 64, 256>>>(out);
}

// round 17
// speedup vs baseline: 1.1071x; 1.1071x over previous
#include <cuda_runtime.h>
#include <cuda_fp16.h>

#define RES 512
#define RANK 32
#define CELLS (RES * RES)
#define N_POINTS (8192 * 128)

// e5m2 dup-pair layout: per plane, per cell (y,x): 64 bytes.
// Word k of 16B group j holds bytes [r@x0, r@x1, r+1@x0, r+1@x1], r = 8j+2k.
// e5m2 byte b decodes EXACTLY to the fp16 with bits (b << 8).
// Plane stride = CELLS*64 = 0x1000000 bytes.
__device__ unsigned char g_tp[3][(size_t)CELLS * 2 * RANK];

// Encoded per-dim bbox of raw pts. Static init; graph replays are idempotent.
__device__ unsigned int g_bbox[6] = {0xFFFFFFFFu, 0xFFFFFFFFu, 0xFFFFFFFFu, 0u, 0u, 0u};

// Affine map: grid = p * g_map[0].{x,y,z} + g_map[1].{x,y,z}
__device__ float4 g_map[2];

__device__ __forceinline__ unsigned int encodeF(float f) {
    unsigned int b = __float_as_uint(f);
    return (b & 0x80000000u) ? ~b : (b | 0x80000000u);
}
__device__ __forceinline__ float decodeF(unsigned int u) {
    return (u & 0x80000000u) ? __uint_as_float(u ^ 0x80000000u)
                             : __uint_as_float(~u);
}

// HW pack-convert: 2 x f32 -> packed e5m2 pair.
__device__ __forceinline__ unsigned short enc2_e5m2(float hi, float lo) {
    unsigned short r;
    asm("cvt.rn.satfinite.e5m2x2.f32 %0, %1, %2;" : "=h"(r) : "f"(hi), "f"(lo));
    return r;
}

// ---------------------------------------------------------------------------
// Kernel 1: bbox + g_map (thread 0). One group (3 float4 = 4 pts) per thread.
// ---------------------------------------------------------------------------
__global__ void __launch_bounds__(256) bbox_kernel(const float4* __restrict__ pts4,
                                                   const float* __restrict__ aabb) {
    const int g = blockIdx.x * 256 + threadIdx.x;
    if (g == 0) {
        float k[3], o[3];
#pragma unroll
        for (int d = 0; d < 3; d++) {
            const float a0 = aabb[d], a1 = aabb[3 + d];
            k[d] = (float)(RES - 1) / (a1 - a0);
            o[d] = -a0 * k[d];
        }
        g_map[0] = make_float4(k[0], k[1], k[2], 0.0f);
        g_map[1] = make_float4(o[0], o[1], o[2], 0.0f);
    }

    const float4 a = __ldg(&pts4[3 * g + 0]);
    const float4 b = __ldg(&pts4[3 * g + 1]);
    const float4 c = __ldg(&pts4[3 * g + 2]);
    const unsigned int FULL = 0xffffffffu;
    const unsigned int rmnx = __reduce_min_sync(FULL, encodeF(fminf(fminf(a.x, a.w), fminf(b.z, c.y))));
    const unsigned int rmxx = __reduce_max_sync(FULL, encodeF(fmaxf(fmaxf(a.x, a.w), fmaxf(b.z, c.y))));
    const unsigned int rmny = __reduce_min_sync(FULL, encodeF(fminf(fminf(a.y, b.x), fminf(b.w, c.z))));
    const unsigned int rmxy = __reduce_max_sync(FULL, encodeF(fmaxf(fmaxf(a.y, b.x), fmaxf(b.w, c.z))));
    const unsigned int rmnz = __reduce_min_sync(FULL, encodeF(fminf(fminf(a.z, b.y), fminf(c.x, c.w))));
    const unsigned int rmxz = __reduce_max_sync(FULL, encodeF(fmaxf(fmaxf(a.z, b.y), fmaxf(c.x, c.w))));

    __shared__ unsigned int smn[3], smx[3];
    if (threadIdx.x < 3) { smn[threadIdx.x] = 0xFFFFFFFFu; smx[threadIdx.x] = 0u; }
    __syncthreads();
    if ((threadIdx.x & 31) == 0) {
        atomicMin(&smn[0], rmnx);
        atomicMin(&smn[1], rmny);
        atomicMin(&smn[2], rmnz);
        atomicMax(&smx[0], rmxx);
        atomicMax(&smx[1], rmxy);
        atomicMax(&smx[2], rmxz);
    }
    __syncthreads();
    if (threadIdx.x < 3) {
        atomicMin(&g_bbox[threadIdx.x], smn[threadIdx.x]);
        atomicMax(&g_bbox[3 + threadIdx.x], smx[threadIdx.x]);
    }
}

// ---------------------------------------------------------------------------
// Kernel 2: [RANK,H,W] f32 -> e5m2 dup-pair layout, bbox-gated.
// ---------------------------------------------------------------------------
__global__ void __launch_bounds__(256) transpose_kernel(const float* __restrict__ gxy,
                                                        const float* __restrict__ gxz,
                                                        const float* __restrict__ gyz,
                                                        const float* __restrict__ aabb) {
    const int plane = blockIdx.y;
    const int c0 = blockIdx.x * 64;
    const int row = c0 >> 9;
    const int col0 = c0 & (RES - 1);

    const int cdim = (plane == 2) ? 1 : 0;
    const int rdim = (plane == 0) ? 1 : 2;

    {   // bbox gate
        const float a0c = aabb[cdim], sc = (float)(RES - 1) / (aabb[3 + cdim] - aabb[cdim]);
        const float a0r = aabb[rdim], sr = (float)(RES - 1) / (aabb[3 + rdim] - aabb[rdim]);
        const float gminc = (decodeF(g_bbox[cdim]) - a0c) * sc;
        const float gmaxc = (decodeF(g_bbox[3 + cdim]) - a0c) * sc;
        const float gminr = (decodeF(g_bbox[rdim]) - a0r) * sr;
        const float gmaxr = (decodeF(g_bbox[3 + rdim]) - a0r) * sr;
        const int cmin = min(max(__float2int_rd(gminc), 0), RES - 1);
        const int cmax = min(min(max(__float2int_rd(gmaxc), 0), RES - 1) + 1, RES - 1);
        const int rmin = min(max(__float2int_rd(gminr), 0), RES - 1);
        const int rmax = min(min(max(__float2int_rd(gmaxr), 0), RES - 1) + 1, RES - 1);
        if (row < rmin || row > rmax || col0 > cmax || col0 + 63 < cmin) return;
    }

    __shared__ float tile[RANK][67];
    const float* __restrict__ src = (plane == 0) ? gxy : (plane == 1) ? gxz : gyz;

    const int t = threadIdx.x;

#pragma unroll
    for (int i = 0; i < 2; i++) {
        const int q = t + i * 256;
        const int r = q >> 4;
        const int c4 = (q & 15) << 2;
        const float4 v = *reinterpret_cast<const float4*>(&src[(size_t)r * CELLS + c0 + c4]);
        tile[r][c4 + 0] = v.x;
        tile[r][c4 + 1] = v.y;
        tile[r][c4 + 2] = v.z;
        tile[r][c4 + 3] = v.w;
    }
    if (t < RANK) {
        const int srccol = (col0 + 64 <= RES - 1) ? (c0 + 64) : (c0 + 63);
        tile[t][64] = src[(size_t)t * CELLS + srccol];
    }
    __syncthreads();

    {
        const int cell = t >> 2;
        const int j = t & 3;
        const int xg = col0 + cell;
        const int nb = (xg < RES - 1) ? cell + 1 : cell;
        uint4 w;
        unsigned int* wp = &w.x;
#pragma unroll
        for (int k = 0; k < 4; k++) {
            const int r0 = 8 * j + 2 * k;
            const unsigned short lo16 = enc2_e5m2(tile[r0][nb], tile[r0][cell]);
            const unsigned short hi16 = enc2_e5m2(tile[r0 + 1][nb], tile[r0 + 1][cell]);
            wp[k] = ((unsigned int)hi16 << 16) | (unsigned int)lo16;
        }
        *reinterpret_cast<uint4*>(&g_tp[plane][((size_t)(c0 + cell) << 6) + (j << 4)]) = w;
    }
}

// ---------------------------------------------------------------------------
// Kernel 3: triplane sample. 4 lanes/point; lane j = ranks 8j..8j+7.
// Head state staged through smem: phase 1, threads 0..191 each compute one
// (point, plane) head task; phase 2, all threads consume via LDS.
// ---------------------------------------------------------------------------
__device__ __forceinline__ uint2 head_plane(float gx, float gy, unsigned int plane_off) {
    const float wx = gx - floorf(gx);
    const float wy = gy - floorf(gy);
    const int x0 = min(max(__float2int_rd(gx), 0), RES - 1);
    const int y0 = min(max(__float2int_rd(gy), 0), RES - 1);
    const unsigned int f = (y0 < RES - 1) ? 1u : 0u;
    const unsigned int o = ((unsigned int)((y0 << 9) + x0) << 6) + plane_off + f;
    const __half2 w = __floats2half2_rn(wx, wy);
    uint2 r;
    r.x = o;
    r.y = *reinterpret_cast<const unsigned int*>(&w);
    return r;
}

__device__ __forceinline__ __half2 as_h2(unsigned int u) {
    return *reinterpret_cast<__half2*>(&u);
}

__device__ __forceinline__ void plane_sample(const uint4& E, const uint4& F,
                                             __half2 w00, __half2 w01,
                                             __half2 w10, __half2 w11,
                                             __half2 s2[4]) {
    const unsigned int* e = &E.x;
    const unsigned int* f = &F.x;
#pragma unroll
    for (int k = 0; k < 4; k++) {
        const unsigned int ex0 = __byte_perm(e[k], 0, 0x2404);  // (r@x0, r+1@x0)
        const unsigned int ex1 = e[k] & 0xFF00FF00u;            // (r@x1, r+1@x1)
        const unsigned int fx0 = __byte_perm(f[k], 0, 0x2404);
        const unsigned int fx1 = f[k] & 0xFF00FF00u;
        __half2 s = __hmul2(as_h2(ex0), w00);
        s = __hfma2(as_h2(ex1), w01, s);
        s = __hfma2(as_h2(fx0), w10, s);
        s2[k] = __hfma2(as_h2(fx1), w11, s);
    }
}

__global__ void __launch_bounds__(256, 8) sample_kernel(const float* __restrict__ pts,
                                                        float* __restrict__ out) {
    // Per-point head record in smem: 8 u32 per point (24 used):
    // [o_xy|f, w_xy, o_xz|f, w_xz, o_yz|f, w_yz, pad, pad]
    __shared__ unsigned int sh[64 * 8];

    const int t = threadIdx.x;
    const int blockPoint0 = blockIdx.x * 64;

    // ---- Phase 1: 192 threads compute one (point, plane) head task each ----
    if (t < 192) {
        const int pl = t % 3;
        const int pt = t / 3;                   // local point 0..63
        const int gpt = blockPoint0 + pt;
        const int d1 = (pl == 2) ? 1 : 0;       // plane column dim
        const int d2 = (pl == 0) ? 1 : 2;       // plane row dim
        const float* Kf = reinterpret_cast<const float*>(&g_map[0]);
        const float* Of = reinterpret_cast<const float*>(&g_map[1]);
        const float c1 = __ldg(&pts[3 * gpt + d1]);
        const float c2 = __ldg(&pts[3 * gpt + d2]);
        const float gx = fmaf(c1, Kf[d1], Of[d1]);
        const float gy = fmaf(c2, Kf[d2], Of[d2]);
        const uint2 r = head_plane(gx, gy, (unsigned int)pl << 24);
        sh[pt * 8 + pl * 2 + 0] = r.x;
        sh[pt * 8 + pl * 2 + 1] = r.y;
    }
    __syncthreads();

    // ---- Phase 2: 4 lanes per point consume the staged head state ----
    const int j = t & 3;                        // rank octet
    const int ptl = t >> 2;                     // local point 0..63
    const unsigned int lo = (unsigned int)j << 4;

    const unsigned int* hp = &sh[ptl * 8];
    const uint4 H1 = *reinterpret_cast<const uint4*>(hp);      // o_xy, w_xy, o_xz, w_xz
    const uint2 H2 = *reinterpret_cast<const uint2*>(hp + 4);  // o_yz, w_yz

    const unsigned int fa = H1.x & 1u;
    const unsigned int oa0 = H1.x + lo - fa;
    const unsigned int oa1 = oa0 + (fa << 15);
    const unsigned int fb = H1.z & 1u;
    const unsigned int ob0 = H1.z + lo - fb;
    const unsigned int ob1 = ob0 + (fb << 15);
    const unsigned int fc = H2.x & 1u;
    const unsigned int oc0 = H2.x + lo - fc;
    const unsigned int oc1 = oc0 + (fc << 15);

    const char* __restrict__ B = reinterpret_cast<const char*>(g_tp);
    const uint4 E0 = *reinterpret_cast<const uint4*>(B + oa0);
    const uint4 F0 = *reinterpret_cast<const uint4*>(B + oa1);
    const uint4 E1 = *reinterpret_cast<const uint4*>(B + ob0);
    const uint4 F1 = *reinterpret_cast<const uint4*>(B + ob1);
    const uint4 E2 = *reinterpret_cast<const uint4*>(B + oc0);
    const uint4 F2 = *reinterpret_cast<const uint4*>(B + oc1);

    // Broadcast weights from packed (wx,wy) words
    const __half2 wx2_0 = as_h2(__byte_perm(H1.y, H1.y, 0x1010));
    const __half2 wy2_0 = as_h2(__byte_perm(H1.y, H1.y, 0x3232));
    const __half2 wx2_1 = as_h2(__byte_perm(H1.w, H1.w, 0x1010));
    const __half2 wy2_1 = as_h2(__byte_perm(H1.w, H1.w, 0x3232));
    const __half2 wx2_2 = as_h2(__byte_perm(H2.y, H2.y, 0x1010));
    const __half2 wy2_2 = as_h2(__byte_perm(H2.y, H2.y, 0x3232));

    const __half2 ONE = __float2half2_rn(1.0f);
    const __half2 ox0 = __hsub2(ONE, wx2_0), oy0 = __hsub2(ONE, wy2_0);
    const __half2 ox1 = __hsub2(ONE, wx2_1), oy1 = __hsub2(ONE, wy2_1);
    const __half2 ox2 = __hsub2(ONE, wx2_2), oy2 = __hsub2(ONE, wy2_2);

    __half2 sA[4], sB[4], sC[4];
    plane_sample(E0, F0, __hmul2(ox0, oy0), __hmul2(wx2_0, oy0),
                 __hmul2(ox0, wy2_0), __hmul2(wx2_0, wy2_0), sA);
    plane_sample(E1, F1, __hmul2(ox1, oy1), __hmul2(wx2_1, oy1),
                 __hmul2(ox1, wy2_1), __hmul2(wx2_1, wy2_1), sB);
    plane_sample(E2, F2, __hmul2(ox2, oy2), __hmul2(wx2_2, oy2),
                 __hmul2(ox2, wy2_2), __hmul2(wx2_2, wy2_2), sC);

    __half2 acc = __hmul2(__hmul2(sA[0], sB[0]), sC[0]);
#pragma unroll
    for (int k = 1; k < 4; k++) {
        acc = __hfma2(__hmul2(sA[k], sB[k]), sC[k], acc);
    }
    float sum = __low2float(acc) + __high2float(acc);

    sum += __shfl_xor_sync(0xffffffffu, sum, 1, 4);
    sum += __shfl_xor_sync(0xffffffffu, sum, 2, 4);

    if (j == 0) {
        out[blockPoint0 + ptl] = exp2f(sum * 0.045084220f);   // exp(sum/32)
    }
}

extern "C" void kernel_launch(void* const* d_in, const int* in_sizes, int n_in,
                              void* d_out, int out_size) {
    const float* pts  = (const float*)d_in[0];
    const float* gxy  = (const float*)d_in[1];
    const float* gxz  = (const float*)d_in[2];
    const float* gyz  = (const float*)d_in[3];
    const float* aabb = (const float*)d_in[4];
    float* out = (float*)d_out;

    bbox_kernel<<<1024, 256>>>((const float4*)pts, aabb);
    transpose_kernel<<<dim3(CELLS / 64, 3), 256>>>(gxy, gxz, gyz, aabb);
    sample_kernel<<<N_POINTS / 64, 256>>>(pts, out);
}